// round 17
// baseline (speedup 1.0000x reference)
#include <cuda_runtime.h>
#include <cuda_bf16.h>
#include <mma.h>
#include <cstdint>

using namespace nvcuda;

#define MAX_N 100000
#define MAX_E 1600000
#define MAX_G 256
#define SCAN_T 512

// Padded feature strides (128B-line aligned rows)
#define LD54  64
#define LD108 128
#define LD216 224

// ---------------------------------------------------------------------------
// Static scratch (16B aligned for vector access)
// ---------------------------------------------------------------------------
__device__ __align__(16) float g_bufA[MAX_N * LD216];
__device__ __align__(16) float g_bufB[MAX_N * LD216];
__device__ __align__(16) float g_dinv[MAX_N];
__device__ __align__(16) float g_pooled[MAX_G * 216 + 64];
__device__ __align__(16) float g_fc1[MAX_G * 1024 + 64];
__device__ __align__(16) float g_W1p[64 * 64];     // 64x64, rows/cols >=54 zero
__device__ __align__(16) float g_W2p[64 * 108];    // 64x108, rows >=54 zero
__device__ __align__(16) float g_W3p[112 * 216];   // 112x216, rows >=108 zero
__device__ int   g_counts[MAX_N];
__device__ int   g_indptr[MAX_N + 1];
__device__ int   g_cursor[MAX_N];
__device__ int   g_blockSums[(MAX_N + SCAN_T - 1) / SCAN_T];
__device__ int   g_done;
__device__ int   g_csrc[MAX_E];

// ---------------------------------------------------------------------------
// Weight padding (K padded to multiple of 8 with zero rows)
// ---------------------------------------------------------------------------
__global__ void pad_w1_kernel(const float* __restrict__ W, float* __restrict__ Wp) {
    int i = blockIdx.x * blockDim.x + threadIdx.x;
    if (i >= 64 * 64) return;
    int r = i / 64, c = i % 64;
    Wp[i] = (r < 54 && c < 54) ? W[r * 54 + c] : 0.f;
}
__global__ void pad_w2_kernel(const float* __restrict__ W, float* __restrict__ Wp) {
    int i = blockIdx.x * blockDim.x + threadIdx.x;
    if (i >= 64 * 108) return;
    int r = i / 108, c = i % 108;
    Wp[i] = (r < 54) ? W[r * 108 + c] : 0.f;
}
__global__ void pad_w3_kernel(const float* __restrict__ W, float* __restrict__ Wp) {
    int i = blockIdx.x * blockDim.x + threadIdx.x;
    if (i >= 112 * 216) return;
    int r = i / 216, c = i % 216;
    Wp[i] = (r < 108) ? W[r * 216 + c] : 0.f;
}

// ---------------------------------------------------------------------------
// CSR construction
// ---------------------------------------------------------------------------
__global__ void zero_counts_kernel(int* counts, int* done, int N) {
    int i = blockIdx.x * blockDim.x + threadIdx.x;
    if (i < N) counts[i] = 0;
    if (i == 0) *done = 0;
}

__global__ void count_kernel(const int* __restrict__ col, int* counts, int E) {
    int i = blockIdx.x * blockDim.x + threadIdx.x;
    if (i < E) atomicAdd(&counts[col[i]], 1);
}

__global__ void bsum_scan_kernel(const int* __restrict__ counts, int* blockSums,
                                 int* done, int N, int nb) {
    __shared__ int s[SCAN_T];
    __shared__ bool last;
    int tid = threadIdx.x;
    int i = blockIdx.x * SCAN_T + tid;
    s[tid] = (i < N) ? counts[i] : 0;
    __syncthreads();
    #pragma unroll
    for (int off = SCAN_T / 2; off > 0; off >>= 1) {
        if (tid < off) s[tid] += s[tid + off];
        __syncthreads();
    }
    if (tid == 0) {
        blockSums[blockIdx.x] = s[0];
        __threadfence();
        int p = atomicAdd(done, 1);
        last = (p == nb - 1);
    }
    __syncthreads();
    if (!last) return;
    int v = (tid < nb) ? blockSums[tid] : 0;
    s[tid] = v;
    __syncthreads();
    #pragma unroll
    for (int off = 1; off < SCAN_T; off <<= 1) {
        int u = (tid >= off) ? s[tid - off] : 0;
        __syncthreads();
        s[tid] += u;
        __syncthreads();
    }
    if (tid < nb) blockSums[tid] = s[tid] - v;
}

__global__ void scan_write_dinv_kernel(const int* __restrict__ counts, const int* __restrict__ blockSums,
                                       int* __restrict__ indptr, int* __restrict__ cursor,
                                       float* __restrict__ dinv, int N) {
    __shared__ int s[SCAN_T];
    int tid = threadIdx.x;
    int i = blockIdx.x * SCAN_T + tid;
    int v = (i < N) ? counts[i] : 0;
    s[tid] = v;
    __syncthreads();
    #pragma unroll
    for (int off = 1; off < SCAN_T; off <<= 1) {
        int u = (tid >= off) ? s[tid - off] : 0;
        __syncthreads();
        s[tid] += u;
        __syncthreads();
    }
    int excl = blockSums[blockIdx.x] + s[tid] - v;
    if (i < N) {
        indptr[i] = excl;
        cursor[i] = excl;
        dinv[i] = rsqrtf((float)v + 1.0f);
    }
    if (i == N - 1) indptr[N] = excl + v;
}

__global__ void fill_kernel(const int* __restrict__ row, const int* __restrict__ col,
                            int* cursor, int* __restrict__ csrc, int E) {
    int e = blockIdx.x * blockDim.x + threadIdx.x;
    if (e >= E) return;
    int pos = atomicAdd(&cursor[col[e]], 1);
    csrc[pos] = row[e];
}

// ---------------------------------------------------------------------------
// Gathers (unchanged — control variables).
// ---------------------------------------------------------------------------
__global__ void gather54_l1_kernel(const float* __restrict__ x,
                                   const int* __restrict__ indptr,
                                   const int* __restrict__ csrc,
                                   const float* __restrict__ dinv,
                                   float* __restrict__ out, int N) {
    const int F = 54, NL = 27;
    int warp = (blockIdx.x * blockDim.x + threadIdx.x) >> 5;
    int lane = threadIdx.x & 31;
    if (warp >= N) return;
    int v = warp;
    int s = indptr[v], e = indptr[v + 1];
    float2 a0 = {0.f, 0.f}, a1 = {0.f, 0.f}, a2 = {0.f, 0.f}, a3 = {0.f, 0.f};
    bool act = lane < NL;
    size_t off2 = (size_t)lane * 2;
    int i = s;
    for (; i + 3 < e; i += 4) {
        int s0 = csrc[i], s1 = csrc[i + 1], s2 = csrc[i + 2], s3 = csrc[i + 3];
        float d0 = dinv[s0], d1 = dinv[s1], d2 = dinv[s2], d3 = dinv[s3];
        if (act) {
            float2 x0 = *reinterpret_cast<const float2*>(x + (size_t)s0 * F + off2);
            float2 x1 = *reinterpret_cast<const float2*>(x + (size_t)s1 * F + off2);
            float2 x2 = *reinterpret_cast<const float2*>(x + (size_t)s2 * F + off2);
            float2 x3 = *reinterpret_cast<const float2*>(x + (size_t)s3 * F + off2);
            a0.x += d0 * x0.x; a0.y += d0 * x0.y;
            a1.x += d1 * x1.x; a1.y += d1 * x1.y;
            a2.x += d2 * x2.x; a2.y += d2 * x2.y;
            a3.x += d3 * x3.x; a3.y += d3 * x3.y;
        }
    }
    for (; i < e; i++) {
        int s0 = csrc[i];
        float d0 = dinv[s0];
        if (act) {
            float2 x0 = *reinterpret_cast<const float2*>(x + (size_t)s0 * F + off2);
            a0.x += d0 * x0.x; a0.y += d0 * x0.y;
        }
    }
    if (act) {
        float dv = dinv[v];
        float2 xv = *reinterpret_cast<const float2*>(x + (size_t)v * F + off2);
        float2 r;
        r.x = dv * ((a0.x + a1.x) + (a2.x + a3.x) + dv * xv.x);
        r.y = dv * ((a0.y + a1.y) + (a2.y + a3.y) + dv * xv.y);
        __stcs(reinterpret_cast<float2*>(out + (size_t)v * LD54 + off2), r);
    }
}

__global__ void gather54_pre_kernel(const float* __restrict__ hs,
                                    const int* __restrict__ indptr,
                                    const int* __restrict__ csrc,
                                    const float* __restrict__ dinv,
                                    float* __restrict__ out, int N) {
    const int NL = 27;
    int warp = (blockIdx.x * blockDim.x + threadIdx.x) >> 5;
    int lane = threadIdx.x & 31;
    if (warp >= N) return;
    int v = warp;
    int s = indptr[v], e = indptr[v + 1];
    float2 a0 = {0.f, 0.f}, a1 = {0.f, 0.f}, a2 = {0.f, 0.f}, a3 = {0.f, 0.f};
    bool act = lane < NL;
    size_t off2 = (size_t)lane * 2;
    int i = s;
    for (; i + 3 < e; i += 4) {
        int s0 = csrc[i], s1 = csrc[i + 1], s2 = csrc[i + 2], s3 = csrc[i + 3];
        if (act) {
            float2 x0 = *reinterpret_cast<const float2*>(hs + (size_t)s0 * LD54 + off2);
            float2 x1 = *reinterpret_cast<const float2*>(hs + (size_t)s1 * LD54 + off2);
            float2 x2 = *reinterpret_cast<const float2*>(hs + (size_t)s2 * LD54 + off2);
            float2 x3 = *reinterpret_cast<const float2*>(hs + (size_t)s3 * LD54 + off2);
            a0.x += x0.x; a0.y += x0.y;
            a1.x += x1.x; a1.y += x1.y;
            a2.x += x2.x; a2.y += x2.y;
            a3.x += x3.x; a3.y += x3.y;
        }
    }
    for (; i < e; i++) {
        int s0 = csrc[i];
        if (act) {
            float2 x0 = *reinterpret_cast<const float2*>(hs + (size_t)s0 * LD54 + off2);
            a0.x += x0.x; a0.y += x0.y;
        }
    }
    if (act) {
        float dv = dinv[v];
        float2 xv = *reinterpret_cast<const float2*>(hs + (size_t)v * LD54 + off2);
        float2 r;
        r.x = dv * ((a0.x + a1.x) + (a2.x + a3.x) + xv.x);
        r.y = dv * ((a0.y + a1.y) + (a2.y + a3.y) + xv.y);
        __stcs(reinterpret_cast<float2*>(out + (size_t)v * LD54 + off2), r);
    }
}

__global__ void gather108_pre_kernel(const float* __restrict__ hs,
                                     const int* __restrict__ indptr,
                                     const int* __restrict__ csrc,
                                     const float* __restrict__ dinv,
                                     float* __restrict__ out, int N) {
    const int NL = 27;
    int warp = (blockIdx.x * blockDim.x + threadIdx.x) >> 5;
    int lane = threadIdx.x & 31;
    if (warp >= N) return;
    int v = warp;
    int s = indptr[v], e = indptr[v + 1];
    float4 a0 = {0.f, 0.f, 0.f, 0.f}, a1 = {0.f, 0.f, 0.f, 0.f};
    float4 a2 = {0.f, 0.f, 0.f, 0.f}, a3 = {0.f, 0.f, 0.f, 0.f};
    bool act = lane < NL;
    size_t off4 = (size_t)lane * 4;
    int i = s;
    for (; i + 3 < e; i += 4) {
        int s0 = csrc[i], s1 = csrc[i + 1], s2 = csrc[i + 2], s3 = csrc[i + 3];
        if (act) {
            float4 x0 = *reinterpret_cast<const float4*>(hs + (size_t)s0 * LD108 + off4);
            float4 x1 = *reinterpret_cast<const float4*>(hs + (size_t)s1 * LD108 + off4);
            float4 x2 = *reinterpret_cast<const float4*>(hs + (size_t)s2 * LD108 + off4);
            float4 x3 = *reinterpret_cast<const float4*>(hs + (size_t)s3 * LD108 + off4);
            a0.x += x0.x; a0.y += x0.y; a0.z += x0.z; a0.w += x0.w;
            a1.x += x1.x; a1.y += x1.y; a1.z += x1.z; a1.w += x1.w;
            a2.x += x2.x; a2.y += x2.y; a2.z += x2.z; a2.w += x2.w;
            a3.x += x3.x; a3.y += x3.y; a3.z += x3.z; a3.w += x3.w;
        }
    }
    for (; i < e; i++) {
        int s0 = csrc[i];
        if (act) {
            float4 x0 = *reinterpret_cast<const float4*>(hs + (size_t)s0 * LD108 + off4);
            a0.x += x0.x; a0.y += x0.y; a0.z += x0.z; a0.w += x0.w;
        }
    }
    if (act) {
        float dv = dinv[v];
        float4 xv = *reinterpret_cast<const float4*>(hs + (size_t)v * LD108 + off4);
        float4 r;
        r.x = dv * ((a0.x + a1.x) + (a2.x + a3.x) + xv.x);
        r.y = dv * ((a0.y + a1.y) + (a2.y + a3.y) + xv.y);
        r.z = dv * ((a0.z + a1.z) + (a2.z + a3.z) + xv.z);
        r.w = dv * ((a0.w + a1.w) + (a2.w + a3.w) + xv.w);
        __stcs(reinterpret_cast<float4*>(out + (size_t)v * LD108 + off4), r);
    }
}

// ---------------------------------------------------------------------------
// Tensor-core GEMM: tf32 WMMA (m16n16k8) with 3-term error compensation.
// C = (Ah+Al)(Bh+Bl) ~= Ah*Bh + Al*Bh + Ah*Bl  (error ~2^-22, fp32-grade)
// Tile 64x64xK8, 256 threads = 8 warps (4 row-strips x 2 col-strips).
// Register-staged prefetch of the next K-tile. REQUIRES K % 8 == 0,
// lda/ldb even, Nc even, ncWrite % 4 == 0.
// ---------------------------------------------------------------------------
template <bool RELU_OUT, bool BIAS, bool SCALE>
__global__ __launch_bounds__(256)
void gemm_tc_kernel(const float* __restrict__ A, int lda,
                    const float* __restrict__ B, int ldb,
                    const float* __restrict__ bias,
                    const float* __restrict__ dinvv,
                    float* __restrict__ C, int ldc,
                    int M, int K, int Nc, int ncWrite) {
    const int BM = 64, BN = 64, BK = 8;
    __shared__ __align__(16) float Ah[BM][BK], Al[BM][BK];
    __shared__ __align__(16) float Bh[BK][BN], Bl[BK][BN];
    __shared__ __align__(16) float Cs[BM][72];

    int tid = threadIdx.x;
    int block_row = blockIdx.y * BM;
    int block_col = blockIdx.x * BN;

    // K-tile staging assignment: A 64x8 and B 8x64, one float2 per thread each.
    int arow = tid >> 2, akk = (tid & 3) * 2;
    int brow = tid >> 5, bcol = (tid & 31) * 2;
    int grA = block_row + arow;
    int gcB = block_col + bcol;
    bool aOK = grA < M;
    bool bOK = gcB < Nc;          // Nc even -> covers both elements

    float2 aR, bR;
    auto loadRegs = [&](int k0) {
        aR = aOK ? *reinterpret_cast<const float2*>(A + (size_t)grA * lda + k0 + akk)
                 : make_float2(0.f, 0.f);
        bR = bOK ? *reinterpret_cast<const float2*>(B + (size_t)(k0 + brow) * ldb + gcB)
                 : make_float2(0.f, 0.f);
    };
    auto storeTiles = [&]() {
        float ah0 = wmma::__float_to_tf32(aR.x);
        float ah1 = wmma::__float_to_tf32(aR.y);
        Ah[arow][akk]     = ah0;  Al[arow][akk]     = aR.x - ah0;
        Ah[arow][akk + 1] = ah1;  Al[arow][akk + 1] = aR.y - ah1;
        float bh0 = wmma::__float_to_tf32(bR.x);
        float bh1 = wmma::__float_to_tf32(bR.y);
        Bh[brow][bcol]     = bh0;  Bl[brow][bcol]     = bR.x - bh0;
        Bh[brow][bcol + 1] = bh1;  Bl[brow][bcol + 1] = bR.y - bh1;
    };

    int wid = tid >> 5;
    int wr = (wid & 3) * 16;      // warp row strip
    int wc = (wid >> 2) * 32;     // warp col strip

    wmma::fragment<wmma::accumulator, 16, 16, 8, float> acc0, acc1;
    wmma::fill_fragment(acc0, 0.f);
    wmma::fill_fragment(acc1, 0.f);

    int tiles = K / BK;
    loadRegs(0);
    storeTiles();
    __syncthreads();

    for (int t = 0; t < tiles; t++) {
        bool more = (t + 1 < tiles);
        if (more) loadRegs((t + 1) * BK);   // LDGs in flight across MMA work

        wmma::fragment<wmma::matrix_a, 16, 16, 8, wmma::precision::tf32, wmma::row_major> fah, fal;
        wmma::fragment<wmma::matrix_b, 16, 16, 8, wmma::precision::tf32, wmma::row_major> fbh0, fbh1, fbl0, fbl1;
        wmma::load_matrix_sync(fah, &Ah[wr][0], BK);
        wmma::load_matrix_sync(fal, &Al[wr][0], BK);
        wmma::load_matrix_sync(fbh0, &Bh[0][wc], BN);
        wmma::load_matrix_sync(fbh1, &Bh[0][wc + 16], BN);
        wmma::load_matrix_sync(fbl0, &Bl[0][wc], BN);
        wmma::load_matrix_sync(fbl1, &Bl[0][wc + 16], BN);

        wmma::mma_sync(acc0, fah, fbh0, acc0);
        wmma::mma_sync(acc1, fah, fbh1, acc1);
        wmma::mma_sync(acc0, fal, fbh0, acc0);
        wmma::mma_sync(acc1, fal, fbh1, acc1);
        wmma::mma_sync(acc0, fah, fbl0, acc0);
        wmma::mma_sync(acc1, fah, fbl1, acc1);

        __syncthreads();
        if (more) {
            storeTiles();
            __syncthreads();
        }
    }

    wmma::store_matrix_sync(&Cs[wr][wc],      acc0, 72, wmma::mem_row_major);
    wmma::store_matrix_sync(&Cs[wr][wc + 16], acc1, 72, wmma::mem_row_major);
    __syncthreads();

    // Epilogue: bias/relu/scale, zero pad columns, vectorized stores.
    int row = tid >> 2, seg = tid & 3;
    int gr = block_row + row;
    if (gr < M) {
        float sc = SCALE ? dinvv[gr] : 1.0f;
        #pragma unroll
        for (int j = 0; j < 4; j++) {
            int c0 = seg * 16 + j * 4;
            int gc = block_col + c0;
            if (gc >= ncWrite) continue;   // ncWrite % 4 == 0
            float4 v = *reinterpret_cast<float4*>(&Cs[row][c0]);
            float outv[4] = {v.x, v.y, v.z, v.w};
            #pragma unroll
            for (int e = 0; e < 4; e++) {
                int g = gc + e;
                float val = 0.f;
                if (g < Nc) {
                    val = outv[e];
                    if (BIAS) val += bias[g];
                    if (RELU_OUT) val = fmaxf(val, 0.f);
                    if (SCALE) val *= sc;
                }
                outv[e] = val;
            }
            *reinterpret_cast<float4*>(C + (size_t)gr * ldc + gc) =
                make_float4(outv[0], outv[1], outv[2], outv[3]);
        }
    }
}

// ---------------------------------------------------------------------------
// Per-graph mean pool. One block per graph, sorted batch. h stride LD216.
// ---------------------------------------------------------------------------
__global__ void pool_kernel(const float* __restrict__ h, const int* __restrict__ batch,
                            float* __restrict__ pooled, int N, int F) {
    int g = blockIdx.x;
    int lo = 0, hi = N;
    while (lo < hi) { int m = (lo + hi) >> 1; if (batch[m] < g) lo = m + 1; else hi = m; }
    int start = lo;
    lo = start; hi = N;
    while (lo < hi) { int m = (lo + hi) >> 1; if (batch[m] < g + 1) lo = m + 1; else hi = m; }
    int end = lo;

    int f = threadIdx.x;
    if (f >= F) return;
    float acc = 0.f;
    for (int v = start; v < end; v++)
        acc += h[(size_t)v * LD216 + f];
    float cnt = (float)(end - start);
    pooled[g * F + f] = acc / fmaxf(cnt, 1.0f);
}

// ---------------------------------------------------------------------------
// Launch
// ---------------------------------------------------------------------------
static inline dim3 ggrid(int M, int Nc) {
    return dim3((Nc + 63) / 64, (M + 63) / 64);
}

extern "C" void kernel_launch(void* const* d_in, const int* in_sizes, int n_in,
                              void* d_out, int out_size) {
    const float* x    = (const float*)d_in[0];
    const int*   ei   = (const int*)d_in[1];
    const int*   batch= (const int*)d_in[2];
    const float* W1   = (const float*)d_in[3];
    const float* b1   = (const float*)d_in[4];
    const float* W2   = (const float*)d_in[5];
    const float* b2   = (const float*)d_in[6];
    const float* W3   = (const float*)d_in[7];
    const float* b3   = (const float*)d_in[8];
    const float* Wf1  = (const float*)d_in[9];
    const float* bf1  = (const float*)d_in[10];
    const float* Wf2  = (const float*)d_in[11];
    const float* bf2  = (const float*)d_in[12];

    int N = in_sizes[0] / 54;
    int E = in_sizes[1] / 2;
    int G = out_size / 128;
    const int* row = ei;
    const int* col = ei + E;

    float *bufA, *bufB, *dinv, *pooled, *fc1, *W1p, *W2p, *W3p;
    int *counts, *indptr, *cursor, *csrc, *blockSums, *done;
    cudaGetSymbolAddress((void**)&bufA, g_bufA);
    cudaGetSymbolAddress((void**)&bufB, g_bufB);
    cudaGetSymbolAddress((void**)&dinv, g_dinv);
    cudaGetSymbolAddress((void**)&pooled, g_pooled);
    cudaGetSymbolAddress((void**)&fc1, g_fc1);
    cudaGetSymbolAddress((void**)&W1p, g_W1p);
    cudaGetSymbolAddress((void**)&W2p, g_W2p);
    cudaGetSymbolAddress((void**)&W3p, g_W3p);
    cudaGetSymbolAddress((void**)&counts, g_counts);
    cudaGetSymbolAddress((void**)&indptr, g_indptr);
    cudaGetSymbolAddress((void**)&cursor, g_cursor);
    cudaGetSymbolAddress((void**)&csrc, g_csrc);
    cudaGetSymbolAddress((void**)&blockSums, g_blockSums);
    cudaGetSymbolAddress((void**)&done, g_done);

    const int T = 256;
    int nb = (N + SCAN_T - 1) / SCAN_T;
    int gatherGrid = (N + 7) / 8;

    // --- CSR build + weight padding ---
    zero_counts_kernel<<<(N + T - 1) / T, T>>>(counts, done, N);
    pad_w1_kernel<<<(64 * 64 + T - 1) / T, T>>>(W1, W1p);
    pad_w2_kernel<<<(64 * 108 + T - 1) / T, T>>>(W2, W2p);
    pad_w3_kernel<<<(112 * 216 + T - 1) / T, T>>>(W3, W3p);
    count_kernel<<<(E + T - 1) / T, T>>>(col, counts, E);
    bsum_scan_kernel<<<nb, SCAN_T>>>(counts, blockSums, done, N, nb);
    scan_write_dinv_kernel<<<nb, SCAN_T>>>(counts, blockSums, indptr, cursor, dinv, N);
    fill_kernel<<<(E + T - 1) / T, T>>>(row, col, cursor, csrc, E);

    // --- Layer 1: K=64 (padded), Nc=54, write pad to 64 ---
    gather54_l1_kernel<<<gatherGrid, T>>>(x, indptr, csrc, dinv, bufA, N);
    gemm_tc_kernel<true, true, true><<<ggrid(N, 54), 256>>>(
        bufA, LD54, W1p, 64, b1, dinv, bufB, LD54, N, 64, 54, 64);

    // --- Layer 2: K=64 (padded), Nc=108, write pad to 128 ---
    gather54_pre_kernel<<<gatherGrid, T>>>(bufB, indptr, csrc, dinv, bufA, N);
    gemm_tc_kernel<true, true, true><<<ggrid(N, 108), 256>>>(
        bufA, LD54, W2p, 108, b2, dinv, bufB, LD108, N, 64, 108, 128);

    // --- Layer 3: K=112 (padded), Nc=216, write pad to 224 ---
    gather108_pre_kernel<<<gatherGrid, T>>>(bufB, indptr, csrc, dinv, bufA, N);
    gemm_tc_kernel<true, true, false><<<ggrid(N, 216), 256>>>(
        bufA, LD108, W3p, 216, b3, nullptr, bufB, LD216, N, 112, 216, 224);

    // --- Global mean pool ---
    pool_kernel<<<G, 256>>>(bufB, batch, pooled, N, 216);

    // --- MLP head: fc1 K=216 (27 k-tiles, exact), fc2 K=1024 ---
    gemm_tc_kernel<true, true, false><<<ggrid(G, 1024), 256>>>(
        pooled, 216, Wf1, 1024, bf1, nullptr, fc1, 1024, G, 216, 1024, 1024);
    gemm_tc_kernel<false, true, false><<<ggrid(G, 128), 256>>>(
        fc1, 1024, Wf2, 128, bf2, nullptr, (float*)d_out, 128, G, 1024, 128, 128);
}